// round 10
// baseline (speedup 1.0000x reference)
#include <cuda_runtime.h>
#include <math.h>

// Linear-chain CRF log-partition, B=64, T=4096, S=64.
//
// Algorithm: linear-domain scan  p' = (p^T E) .* exp(s_t),  E = exp(transition),
// with exact block renormalization every 4 steps (log-scale tracked in double).
// 128 chains: forward half-scan + backward half-scan per batch, combined by a
// tiny second kernel:  out[b] = log(Af^T E r) + Lf + Lb.

#define BATCH 64
#define SEQT  4096
#define NSTATE 64
#define NSTEP 2047           // steps per half-chain (fw: t=1..2047, bw: t=4094..2048)

__device__ float  g_vec[128 * 64];   // final normalized vectors per chain
__device__ double g_L[128];          // accumulated log-scales per chain

__global__ void __launch_bounds__(128)
crf_scan_kernel(const float* __restrict__ scores,
                const float* __restrict__ trans,
                const float* __restrict__ source,
                const float* __restrict__ sink)
{
    __shared__ float sp[64];     // current state vector (linear domain, renormalized)
    __shared__ float paux[64];   // k=1 partial sums
    __shared__ float wred[2];    // warp maxima for renorm

    const int c    = blockIdx.x;        // chain id
    const int b    = c >> 1;
    const int dir  = c & 1;             // 0 = forward, 1 = backward
    const int tid  = threadIdx.x;
    const int j    = tid & 63;          // output state owned by this thread
    const int k    = tid >> 6;          // which half of the inner sum (0/1)
    const int warp = tid >> 5;
    const int lane = tid & 31;

    // --- E half-column in registers (exp of transition), computed once ---
    float E[32];
#pragma unroll
    for (int m = 0; m < 32; ++m) {
        const int i = 32 * k + m;
        // forward: out j sums over i  -> E[i][j]
        // backward: out i(=j) sums over jj -> E[j][jj]
        const float tv = dir ? trans[j * 64 + i] : trans[i * 64 + j];
        E[m] = __expf(tv);
    }

    const float* sbase = scores + (size_t)b * SEQT * NSTATE;

    // --- init state ---
    if (k == 0) {
        float s0;
        if (dir == 0) s0 = source[j] + sbase[j];                       // alpha_0 (w/o logS)
        else          s0 = sink[j] + sbase[(SEQT - 1) * NSTATE + j];   // r_{T-1}
        float v0 = __expf(s0);
        if (dir == 0) v0 *= 64.0f;     // the reference's +log(S) at t==0
        sp[j] = v0;
    }
    __syncthreads();

    double L = 0.0;

    const float* p0   = sbase + (dir == 0 ? 1 * NSTATE : (SEQT - 2) * NSTATE) + j;
    const int    sstr = (dir == 0) ? NSTATE : -NSTATE;

    // emission prefetch pipeline (k==0 threads only), depth 8
    float sc[8];
    if (k == 0) {
#pragma unroll
        for (int u = 0; u < 8; ++u) sc[u] = __ldg(p0 + u * sstr);
    }

    int q = 0;
    for (int it = 0; it < 255; ++it) {       // 255*8 = 2040 main steps
#pragma unroll
        for (int u = 0; u < 8; ++u, ++q) {
            float eV = 0.0f;
            if (k == 0) {
                eV = __expf(sc[u]);
                int qn = q + 8;
                if (qn > NSTEP - 1) qn = NSTEP - 1;   // clamped (harmless) prefetch
                sc[u] = __ldg(p0 + qn * sstr);
            }
            // half matvec: part = sum_{m} sp[32k+m] * E[m]
            float a0 = 0.f, a1 = 0.f, a2 = 0.f, a3 = 0.f;
#pragma unroll
            for (int m = 0; m < 32; m += 4) {
                a0 = fmaf(sp[32 * k + m + 0], E[m + 0], a0);
                a1 = fmaf(sp[32 * k + m + 1], E[m + 1], a1);
                a2 = fmaf(sp[32 * k + m + 2], E[m + 2], a2);
                a3 = fmaf(sp[32 * k + m + 3], E[m + 3], a3);
            }
            const float part = (a0 + a1) + (a2 + a3);
            if (k) paux[j] = part;
            __syncthreads();                              // partials visible

            if ((u & 3) != 3) {
                // normal step
                if (!k) sp[j] = (part + paux[j]) * eV;
                __syncthreads();                          // sp visible
            } else {
                // renorm step (every 4th): exact block max
                float v = 0.0f;
                if (!k) {
                    v = (part + paux[j]) * eV;
                    float wm = v;
#pragma unroll
                    for (int o = 16; o; o >>= 1)
                        wm = fmaxf(wm, __shfl_xor_sync(0xffffffffu, wm, o));
                    if (lane == 0) wred[warp] = wm;
                }
                __syncthreads();
                const float mx = fmaxf(wred[0], wred[1]);
                if (!k) sp[j] = v * __frcp_rn(mx);
                L += (double)logf(mx);
                __syncthreads();
            }
        }
    }

    // --- tail: 7 steps, direct loads, renorm every step ---
    for (; q < NSTEP; ++q) {
        float eV = 0.0f;
        if (k == 0) eV = __expf(__ldg(p0 + q * sstr));
        float a0 = 0.f, a1 = 0.f, a2 = 0.f, a3 = 0.f;
#pragma unroll
        for (int m = 0; m < 32; m += 4) {
            a0 = fmaf(sp[32 * k + m + 0], E[m + 0], a0);
            a1 = fmaf(sp[32 * k + m + 1], E[m + 1], a1);
            a2 = fmaf(sp[32 * k + m + 2], E[m + 2], a2);
            a3 = fmaf(sp[32 * k + m + 3], E[m + 3], a3);
        }
        const float part = (a0 + a1) + (a2 + a3);
        if (k) paux[j] = part;
        __syncthreads();
        float v = 0.0f;
        if (!k) {
            v = (part + paux[j]) * eV;
            float wm = v;
#pragma unroll
            for (int o = 16; o; o >>= 1)
                wm = fmaxf(wm, __shfl_xor_sync(0xffffffffu, wm, o));
            if (lane == 0) wred[warp] = wm;
        }
        __syncthreads();
        const float mx = fmaxf(wred[0], wred[1]);
        if (!k) sp[j] = v * __frcp_rn(mx);
        L += (double)logf(mx);
        __syncthreads();
    }

    // --- epilogue: final exact renorm, store chain result ---
    if (!k) {
        float wm = sp[j];
#pragma unroll
        for (int o = 16; o; o >>= 1)
            wm = fmaxf(wm, __shfl_xor_sync(0xffffffffu, wm, o));
        if (lane == 0) wred[warp] = wm;
    }
    __syncthreads();
    const float mx = fmaxf(wred[0], wred[1]);
    if (!k) g_vec[c * 64 + j] = sp[j] * __frcp_rn(mx);
    if (tid == 0) g_L[c] = L + (double)logf(mx);
}

// out[b] = log( sum_{i,j} Af[i] * E[i][j] * r[j] ) + Lf + Lb
__global__ void __launch_bounds__(64)
crf_combine_kernel(const float* __restrict__ trans, float* __restrict__ out)
{
    __shared__ float af[64];
    __shared__ float rr[64];
    __shared__ float wsum[2];

    const int b    = blockIdx.x;
    const int tid  = threadIdx.x;
    const int warp = tid >> 5;
    const int lane = tid & 31;

    af[tid] = g_vec[(2 * b) * 64 + tid];
    rr[tid] = g_vec[(2 * b + 1) * 64 + tid];
    __syncthreads();

    // c_j = sum_i af[i] * exp(T[i][j])
    float cj = 0.0f;
#pragma unroll 8
    for (int i = 0; i < 64; ++i)
        cj = fmaf(af[i], __expf(trans[i * 64 + tid]), cj);
    float pj = cj * rr[tid];

#pragma unroll
    for (int o = 16; o; o >>= 1)
        pj += __shfl_xor_sync(0xffffffffu, pj, o);
    if (lane == 0) wsum[warp] = pj;
    __syncthreads();

    if (tid == 0) {
        const double s = (double)wsum[0] + (double)wsum[1];
        out[b] = (float)(log(s) + g_L[2 * b] + g_L[2 * b + 1]);
    }
}

extern "C" void kernel_launch(void* const* d_in, const int* in_sizes, int n_in,
                              void* d_out, int out_size)
{
    const float* scores = (const float*)d_in[0];   // (64, 4096, 64)
    const float* trans  = (const float*)d_in[1];   // (64, 64)
    const float* source = (const float*)d_in[2];   // (64,)
    const float* sink   = (const float*)d_in[3];   // (64,)
    float* out = (float*)d_out;                    // (64,)

    crf_scan_kernel<<<128, 128>>>(scores, trans, source, sink);
    crf_combine_kernel<<<64, 64>>>(trans, out);
}

// round 11
// speedup vs baseline: 1.0001x; 1.0001x over previous
#include <cuda_runtime.h>
#include <math.h>

// Linear-chain CRF log-partition, B=64, T=4096, S=64.
//
// Algorithm: linear-domain scan  p' = (p^T E) .* exp(s_t),  E = exp(transition),
// with exact block renormalization every 4 steps (log-scale tracked in double).
// 128 chains: forward half-scan + backward half-scan per batch, combined by a
// tiny second kernel:  out[b] = log(Af^T E r) + Lf + Lb.

#define BATCH 64
#define SEQT  4096
#define NSTATE 64
#define NSTEP 2047           // steps per half-chain (fw: t=1..2047, bw: t=4094..2048)

__device__ float  g_vec[128 * 64];   // final normalized vectors per chain
__device__ double g_L[128];          // accumulated log-scales per chain

__global__ void __launch_bounds__(128)
crf_scan_kernel(const float* __restrict__ scores,
                const float* __restrict__ trans,
                const float* __restrict__ source,
                const float* __restrict__ sink)
{
    __shared__ float sp[64];     // current state vector (linear domain, renormalized)
    __shared__ float paux[64];   // k=1 partial sums
    __shared__ float wred[2];    // warp maxima for renorm

    const int c    = blockIdx.x;        // chain id
    const int b    = c >> 1;
    const int dir  = c & 1;             // 0 = forward, 1 = backward
    const int tid  = threadIdx.x;
    const int j    = tid & 63;          // output state owned by this thread
    const int k    = tid >> 6;          // which half of the inner sum (0/1)
    const int warp = tid >> 5;
    const int lane = tid & 31;

    // --- E half-column in registers (exp of transition), computed once ---
    float E[32];
#pragma unroll
    for (int m = 0; m < 32; ++m) {
        const int i = 32 * k + m;
        // forward: out j sums over i  -> E[i][j]
        // backward: out i(=j) sums over jj -> E[j][jj]
        const float tv = dir ? trans[j * 64 + i] : trans[i * 64 + j];
        E[m] = __expf(tv);
    }

    const float* sbase = scores + (size_t)b * SEQT * NSTATE;

    // --- init state ---
    if (k == 0) {
        float s0;
        if (dir == 0) s0 = source[j] + sbase[j];                       // alpha_0 (w/o logS)
        else          s0 = sink[j] + sbase[(SEQT - 1) * NSTATE + j];   // r_{T-1}
        float v0 = __expf(s0);
        if (dir == 0) v0 *= 64.0f;     // the reference's +log(S) at t==0
        sp[j] = v0;
    }
    __syncthreads();

    double L = 0.0;

    const float* p0   = sbase + (dir == 0 ? 1 * NSTATE : (SEQT - 2) * NSTATE) + j;
    const int    sstr = (dir == 0) ? NSTATE : -NSTATE;

    // emission prefetch pipeline (k==0 threads only), depth 8
    float sc[8];
    if (k == 0) {
#pragma unroll
        for (int u = 0; u < 8; ++u) sc[u] = __ldg(p0 + u * sstr);
    }

    int q = 0;
    for (int it = 0; it < 255; ++it) {       // 255*8 = 2040 main steps
#pragma unroll
        for (int u = 0; u < 8; ++u, ++q) {
            float eV = 0.0f;
            if (k == 0) {
                eV = __expf(sc[u]);
                int qn = q + 8;
                if (qn > NSTEP - 1) qn = NSTEP - 1;   // clamped (harmless) prefetch
                sc[u] = __ldg(p0 + qn * sstr);
            }
            // half matvec: part = sum_{m} sp[32k+m] * E[m]
            float a0 = 0.f, a1 = 0.f, a2 = 0.f, a3 = 0.f;
#pragma unroll
            for (int m = 0; m < 32; m += 4) {
                a0 = fmaf(sp[32 * k + m + 0], E[m + 0], a0);
                a1 = fmaf(sp[32 * k + m + 1], E[m + 1], a1);
                a2 = fmaf(sp[32 * k + m + 2], E[m + 2], a2);
                a3 = fmaf(sp[32 * k + m + 3], E[m + 3], a3);
            }
            const float part = (a0 + a1) + (a2 + a3);
            if (k) paux[j] = part;
            __syncthreads();                              // partials visible

            if ((u & 3) != 3) {
                // normal step
                if (!k) sp[j] = (part + paux[j]) * eV;
                __syncthreads();                          // sp visible
            } else {
                // renorm step (every 4th): exact block max
                float v = 0.0f;
                if (!k) {
                    v = (part + paux[j]) * eV;
                    float wm = v;
#pragma unroll
                    for (int o = 16; o; o >>= 1)
                        wm = fmaxf(wm, __shfl_xor_sync(0xffffffffu, wm, o));
                    if (lane == 0) wred[warp] = wm;
                }
                __syncthreads();
                const float mx = fmaxf(wred[0], wred[1]);
                if (!k) sp[j] = v * __frcp_rn(mx);
                L += (double)logf(mx);
                __syncthreads();
            }
        }
    }

    // --- tail: 7 steps, direct loads, renorm every step ---
    for (; q < NSTEP; ++q) {
        float eV = 0.0f;
        if (k == 0) eV = __expf(__ldg(p0 + q * sstr));
        float a0 = 0.f, a1 = 0.f, a2 = 0.f, a3 = 0.f;
#pragma unroll
        for (int m = 0; m < 32; m += 4) {
            a0 = fmaf(sp[32 * k + m + 0], E[m + 0], a0);
            a1 = fmaf(sp[32 * k + m + 1], E[m + 1], a1);
            a2 = fmaf(sp[32 * k + m + 2], E[m + 2], a2);
            a3 = fmaf(sp[32 * k + m + 3], E[m + 3], a3);
        }
        const float part = (a0 + a1) + (a2 + a3);
        if (k) paux[j] = part;
        __syncthreads();
        float v = 0.0f;
        if (!k) {
            v = (part + paux[j]) * eV;
            float wm = v;
#pragma unroll
            for (int o = 16; o; o >>= 1)
                wm = fmaxf(wm, __shfl_xor_sync(0xffffffffu, wm, o));
            if (lane == 0) wred[warp] = wm;
        }
        __syncthreads();
        const float mx = fmaxf(wred[0], wred[1]);
        if (!k) sp[j] = v * __frcp_rn(mx);
        L += (double)logf(mx);
        __syncthreads();
    }

    // --- epilogue: final exact renorm, store chain result ---
    if (!k) {
        float wm = sp[j];
#pragma unroll
        for (int o = 16; o; o >>= 1)
            wm = fmaxf(wm, __shfl_xor_sync(0xffffffffu, wm, o));
        if (lane == 0) wred[warp] = wm;
    }
    __syncthreads();
    const float mx = fmaxf(wred[0], wred[1]);
    if (!k) g_vec[c * 64 + j] = sp[j] * __frcp_rn(mx);
    if (tid == 0) g_L[c] = L + (double)logf(mx);
}

// out[b] = log( sum_{i,j} Af[i] * E[i][j] * r[j] ) + Lf + Lb
__global__ void __launch_bounds__(64)
crf_combine_kernel(const float* __restrict__ trans, float* __restrict__ out)
{
    __shared__ float af[64];
    __shared__ float rr[64];
    __shared__ float wsum[2];

    const int b    = blockIdx.x;
    const int tid  = threadIdx.x;
    const int warp = tid >> 5;
    const int lane = tid & 31;

    af[tid] = g_vec[(2 * b) * 64 + tid];
    rr[tid] = g_vec[(2 * b + 1) * 64 + tid];
    __syncthreads();

    // c_j = sum_i af[i] * exp(T[i][j])
    float cj = 0.0f;
#pragma unroll 8
    for (int i = 0; i < 64; ++i)
        cj = fmaf(af[i], __expf(trans[i * 64 + tid]), cj);
    float pj = cj * rr[tid];

#pragma unroll
    for (int o = 16; o; o >>= 1)
        pj += __shfl_xor_sync(0xffffffffu, pj, o);
    if (lane == 0) wsum[warp] = pj;
    __syncthreads();

    if (tid == 0) {
        const double s = (double)wsum[0] + (double)wsum[1];
        out[b] = (float)(log(s) + g_L[2 * b] + g_L[2 * b + 1]);
    }
}

extern "C" void kernel_launch(void* const* d_in, const int* in_sizes, int n_in,
                              void* d_out, int out_size)
{
    const float* scores = (const float*)d_in[0];   // (64, 4096, 64)
    const float* trans  = (const float*)d_in[1];   // (64, 64)
    const float* source = (const float*)d_in[2];   // (64,)
    const float* sink   = (const float*)d_in[3];   // (64,)
    float* out = (float*)d_out;                    // (64,)

    crf_scan_kernel<<<128, 128>>>(scores, trans, source, sink);
    crf_combine_kernel<<<64, 64>>>(trans, out);
}

// round 14
// speedup vs baseline: 1.4012x; 1.4011x over previous
#include <cuda_runtime.h>
#include <stdint.h>
#include <math.h>

// Linear-chain CRF log-partition, B=64, T=4096, S=64.
//
// Linear-domain scan  p' = (p^T E) .* (exp(s_t) * 2^-7),  E = exp(transition).
// 128 chains (fwd + bwd half-scan per batch). Per step: one 64-term dot per
// thread via fma.rn.f32x2 + ld.shared.v2.b64, double-buffered state, ONE
// barrier per step. Renormalization is folded into the next step's emission
// scale (no extra barrier); the constant 2^-7 per-step scale is compensated
// exactly by NSTEP*7*ln2 in the log accumulator.

typedef unsigned long long u64;
typedef unsigned int       u32;

#define BATCH  64
#define SEQT   4096
#define NSTEP  2047          // steps per half-chain
#define NGROUP 127           // groups of 16 steps (127*16 = 2032)
#define NTAIL  15            // 2032 + 15 = 2047

__device__ float  g_vec[128 * 64];   // final normalized vectors per chain
__device__ double g_L[128];          // accumulated log-scales per chain

__device__ __forceinline__ u32 smem_u32(const void* p) {
    u32 a;
    asm("{ .reg .u64 t; cvta.to.shared.u64 t, %1; cvt.u32.u64 %0, t; }"
        : "=r"(a) : "l"(p));
    return a;
}

#define FFMA2(acc, a, b) \
    asm("fma.rn.f32x2 %0, %1, %2, %0;" : "+l"(acc) : "l"(a), "l"(b))
#define ADDX2(d, a, b) \
    asm("add.rn.f32x2 %0, %1, %2;" : "=l"(d) : "l"(a), "l"(b))

// 64-term dot of smem state vector (at shared addr) with packed column E2[32].
__device__ __forceinline__ float dot64(u32 addr, const u64* E2) {
    u64 a0 = 0ull, a1 = 0ull, a2 = 0ull, a3 = 0ull;
#pragma unroll
    for (int h = 0; h < 8; ++h) {
        u64 s0, s1, s2, s3;
        asm volatile("ld.shared.v2.b64 {%0,%1}, [%2];"
                     : "=l"(s0), "=l"(s1) : "r"(addr + h * 32));
        asm volatile("ld.shared.v2.b64 {%0,%1}, [%2];"
                     : "=l"(s2), "=l"(s3) : "r"(addr + h * 32 + 16));
        FFMA2(a0, s0, E2[4 * h + 0]);
        FFMA2(a1, s1, E2[4 * h + 1]);
        FFMA2(a2, s2, E2[4 * h + 2]);
        FFMA2(a3, s3, E2[4 * h + 3]);
    }
    u64 t0, t1;
    ADDX2(t0, a0, a1);
    ADDX2(t1, a2, a3);
    ADDX2(t0, t0, t1);
    float lo, hi;
    asm("mov.b64 {%0,%1}, %2;" : "=f"(lo), "=f"(hi) : "l"(t0));
    return lo + hi;
}

__global__ void __launch_bounds__(64)
crf_scan_kernel(const float* __restrict__ scores,
                const float* __restrict__ trans,
                const float* __restrict__ source,
                const float* __restrict__ sink)
{
    __shared__ __align__(16) float sp[2][64];   // double-buffered state
    __shared__ float wred[2];                    // warp maxima for renorm

    const int c    = blockIdx.x;     // chain id
    const int b    = c >> 1;
    const int dir  = c & 1;          // 0 = forward, 1 = backward
    const int j    = threadIdx.x;    // output state owned by this thread
    const int warp = j >> 5;
    const int lane = j & 31;

    // Packed E column for this output (inner index i packed in pairs).
    u64 E2[32];
#pragma unroll
    for (int i2 = 0; i2 < 32; ++i2) {
        const int i0 = 2 * i2, i1 = 2 * i2 + 1;
        const float e0 = __expf(dir ? trans[j * 64 + i0] : trans[i0 * 64 + j]);
        const float e1 = __expf(dir ? trans[j * 64 + i1] : trans[i1 * 64 + j]);
        asm("mov.b64 %0, {%1,%2};" : "=l"(E2[i2]) : "f"(e0), "f"(e1));
    }

    const float* sbase = scores + (size_t)b * SEQT * 64;

    // init state
    {
        float s0 = dir ? (sink[j] + sbase[(SEQT - 1) * 64 + j])
                       : (source[j] + sbase[j]);
        float v0 = __expf(s0);
        if (!dir) v0 *= 64.0f;       // reference's +log(S) at t==0
        sp[0][j] = v0;
    }
    if (j < 2) wred[j] = 1.0f;
    __syncthreads();

    const u32 spa0 = smem_u32(&sp[0][0]);
    const u32 spa1 = smem_u32(&sp[1][0]);

    const float* p0   = sbase + (dir ? (SEQT - 2) * 64 : 64) + j;
    const int    sstr = dir ? -64 : 64;

    // emission prefetch ring, depth 8
    float sc[8];
#pragma unroll
    for (int u = 0; u < 8; ++u) sc[u] = __ldg(p0 + u * sstr);

    double L   = 0.0;
    int    q   = 0;
    int    p   = 0;
    float  v   = 0.0f;
    float  rmx = 1.0f;               // pending 1/mx from previous group

    for (int g = 0; g < NGROUP; ++g) {
#pragma unroll
        for (int h8 = 0; h8 < 2; ++h8) {
#pragma unroll
            for (int u = 0; u < 8; ++u) {
                float eV = __expf(sc[u]) * 0.0078125f;   // exact 2^-7 fold
                if (h8 == 0 && u == 0) eV *= rmx;        // consume pending renorm
                int qn = q + 8; if (qn > NSTEP - 1) qn = NSTEP - 1;
                sc[u] = __ldg(p0 + qn * sstr);

                v = dot64(p ? spa1 : spa0, E2) * eV;
                sp[p ^ 1][j] = v;
                p ^= 1;
                ++q;

                if (h8 == 1 && u == 7) {                 // group-end max
                    float wm = v;
#pragma unroll
                    for (int o = 16; o; o >>= 1)
                        wm = fmaxf(wm, __shfl_xor_sync(0xffffffffu, wm, o));
                    if (lane == 0) wred[warp] = wm;
                }
                __syncthreads();                         // the ONE barrier
            }
        }
        const float mx = fmaxf(wred[0], wred[1]);
        L += (double)logf(mx);
        rmx = __frcp_rn(mx);
    }

    // tail: 15 steps (fully unrolled so the ring index stays compile-time)
#pragma unroll
    for (int t = 0; t < NTAIL; ++t) {
        const int u = t & 7;
        float eV = __expf(sc[u]) * 0.0078125f;
        if (t == 0) eV *= rmx;
        int qn = q + 8; if (qn > NSTEP - 1) qn = NSTEP - 1;
        sc[u] = __ldg(p0 + qn * sstr);

        v = dot64(p ? spa1 : spa0, E2) * eV;
        sp[p ^ 1][j] = v;
        p ^= 1;
        ++q;
        __syncthreads();
    }

    // epilogue: final exact renorm, store chain result
    {
        float wm = v;
#pragma unroll
        for (int o = 16; o; o >>= 1)
            wm = fmaxf(wm, __shfl_xor_sync(0xffffffffu, wm, o));
        if (lane == 0) wred[warp] = wm;
    }
    __syncthreads();
    const float mxf = fmaxf(wred[0], wred[1]);
    g_vec[c * 64 + j] = v * __frcp_rn(mxf);
    if (j == 0)
        g_L[c] = L + (double)logf(mxf)
               + (double)NSTEP * (7.0 * 0.6931471805599453);  // undo 2^-7/step
}

// out[b] = log( sum_{i,j} Af[i] * E[i][j] * r[j] ) + Lf + Lb
__global__ void __launch_bounds__(64)
crf_combine_kernel(const float* __restrict__ trans, float* __restrict__ out)
{
    __shared__ float af[64];
    __shared__ float rr[64];
    __shared__ float wsum[2];

    const int b    = blockIdx.x;
    const int tid  = threadIdx.x;
    const int warp = tid >> 5;
    const int lane = tid & 31;

    af[tid] = g_vec[(2 * b) * 64 + tid];
    rr[tid] = g_vec[(2 * b + 1) * 64 + tid];
    __syncthreads();

    float cj = 0.0f;
#pragma unroll 8
    for (int i = 0; i < 64; ++i)
        cj = fmaf(af[i], __expf(trans[i * 64 + tid]), cj);
    float pj = cj * rr[tid];

#pragma unroll
    for (int o = 16; o; o >>= 1)
        pj += __shfl_xor_sync(0xffffffffu, pj, o);
    if (lane == 0) wsum[warp] = pj;
    __syncthreads();

    if (tid == 0) {
        const double s = (double)wsum[0] + (double)wsum[1];
        out[b] = (float)(log(s) + g_L[2 * b] + g_L[2 * b + 1]);
    }
}

extern "C" void kernel_launch(void* const* d_in, const int* in_sizes, int n_in,
                              void* d_out, int out_size)
{
    const float* scores = (const float*)d_in[0];   // (64, 4096, 64)
    const float* trans  = (const float*)d_in[1];   // (64, 64)
    const float* source = (const float*)d_in[2];   // (64,)
    const float* sink   = (const float*)d_in[3];   // (64,)
    float* out = (float*)d_out;                    // (64,)

    crf_scan_kernel<<<128, 64>>>(scores, trans, source, sink);
    crf_combine_kernel<<<64, 64>>>(trans, out);
}